// round 9
// baseline (speedup 1.0000x reference)
#include <cuda_runtime.h>
#include <cuda_bf16.h>
#include <cuda_fp16.h>
#include <math.h>
#include <stdint.h>

// ---------------------------------------------------------------------------
// TensoRF_Slim: fused TensoRF feature sampling + volume rendering.
// Round 7: spatial binning (32^3 Morton counting sort) + two-phase render.
// Phase A processes points in sorted order -> warp-local gather footprints
// (~9.5 texels/axis) -> far fewer L1tex wavefronts per gather instruction
// (measured bound: L1=81.3%). Phase B does the per-ray fp64 alpha chain
// (protected R3 fix), scan and reduce.
// ---------------------------------------------------------------------------

#define MAXG 300
#define GG (MAXG * MAXG)
#define NBINS 32768              // 32^3
#define MAXPTS (4096 * 256)

// Device-global scratch (static allocation; no runtime allocs allowed).
__device__ __align__(16) __half g_dplanesH[3 * GG * 8];    // (3, G*G, 8)
__device__ __align__(16) __half g_aplanesH[3 * GG * 24];   // (3, G*G, 24)
__device__ __align__(16) __half g_dlinesH[3 * MAXG * 8];   // (3, G, 8)
__device__ __align__(16) __half g_alinesH[3 * MAXG * 24];  // (3, G, 24)

__device__ int    g_cnt[NBINS];
__device__ int    g_off[NBINS];
__device__ float4 g_sorted[MAXPTS];   // normalized p.xyz + orig idx
__device__ float4 g_feat[MAXPTS];     // sigma_feat, rgb0, rgb1, rgb2

// ---------------------------------------------------------------------------
// Fused transpose: all four tensors (3, C, P) fp32 -> (3, P, C) fp16.
// ---------------------------------------------------------------------------
__global__ void transpose_all_kernel(const float* __restrict__ dp,
                                     const float* __restrict__ ap,
                                     const float* __restrict__ dl,
                                     const float* __restrict__ al,
                                     int G) {
    __shared__ float tile[32][25];
    int type = blockIdx.y / 3;
    int i    = blockIdx.y % 3;

    int P, C;
    const float* src;
    __half* dst;
    switch (type) {
        case 0:  P = G * G; C = 8;  src = dp; dst = g_dplanesH; break;
        case 1:  P = G * G; C = 24; src = ap; dst = g_aplanesH; break;
        case 2:  P = G;     C = 8;  src = dl; dst = g_dlinesH;  break;
        default: P = G;     C = 24; src = al; dst = g_alinesH;  break;
    }
    int p0 = blockIdx.x * 32;
    if (p0 >= P) return;

    src += (size_t)i * C * P;
    dst += (size_t)i * P * C;

    for (int j = threadIdx.x; j < C * 32; j += blockDim.x) {
        int c = j >> 5, pp = j & 31;
        int p = p0 + pp;
        tile[pp][c] = (p < P) ? src[(size_t)c * P + p] : 0.f;
    }
    __syncthreads();
    for (int j = threadIdx.x; j < C * 32; j += blockDim.x) {
        int pp = j / C, c = j - pp * C;
        int p = p0 + pp;
        if (p < P) dst[(size_t)p * C + c] = __float2half_rn(tile[pp][c]);
    }
}

// ---------------------------------------------------------------------------
// Binning: 5-bit Morton per axis -> 15-bit bin.
// ---------------------------------------------------------------------------
__device__ __forceinline__ uint32_t part1by2_5(uint32_t x) {
    x &= 31u;
    x = (x | (x << 8)) & 0x100Fu;
    x = (x | (x << 4)) & 0x10C3u;
    x = (x | (x << 2)) & 0x1249u;
    return x;
}

__device__ __forceinline__ void normalize_p(const float* __restrict__ xyz,
                                            const float* __restrict__ aabb,
                                            int i, float* p) {
#pragma unroll
    for (int k = 0; k < 3; k++) {
        float lo = aabb[k], hi = aabb[3 + k];
        float inv = 2.0f / (hi - lo);
        p[k] = (xyz[i * 3 + k] - lo) * inv - 1.0f;
    }
}

__device__ __forceinline__ uint32_t bin_of(const float* p) {
    uint32_t q[3];
#pragma unroll
    for (int k = 0; k < 3; k++) {
        int v = (int)((p[k] + 1.0f) * 16.0f);
        q[k] = (uint32_t)max(0, min(v, 31));
    }
    return part1by2_5(q[0]) | (part1by2_5(q[1]) << 1) | (part1by2_5(q[2]) << 2);
}

__global__ void clear_kernel() {
    int i = blockIdx.x * blockDim.x + threadIdx.x;
    if (i < NBINS) g_cnt[i] = 0;
}

__global__ void hist_kernel(const float* __restrict__ xyz,
                            const float* __restrict__ aabb, int N) {
    int i = blockIdx.x * blockDim.x + threadIdx.x;
    if (i >= N) return;
    float p[3];
    normalize_p(xyz, aabb, i, p);
    atomicAdd(&g_cnt[bin_of(p)], 1);
}

// Single block, 1024 threads: exclusive prefix sum of g_cnt -> g_off.
__global__ void scan_kernel() {
    __shared__ int wsum[32];
    int t = threadIdx.x;
    int lane = t & 31, w = t >> 5;
    const int ITEMS = NBINS / 1024;   // 32
    int base = t * ITEMS;

    int local[ITEMS];
    int sum = 0;
#pragma unroll
    for (int k = 0; k < ITEMS; k++) { local[k] = g_cnt[base + k]; sum += local[k]; }

    // inclusive scan of per-thread sums
    int incl = sum;
#pragma unroll
    for (int o = 1; o < 32; o <<= 1) {
        int v = __shfl_up_sync(0xFFFFFFFFu, incl, o);
        if (lane >= o) incl += v;
    }
    if (lane == 31) wsum[w] = incl;
    __syncthreads();
    if (w == 0) {
        int v = (lane < 32) ? wsum[lane] : 0;
        int iv = v;
#pragma unroll
        for (int o = 1; o < 32; o <<= 1) {
            int u = __shfl_up_sync(0xFFFFFFFFu, iv, o);
            if (lane >= o) iv += u;
        }
        wsum[lane] = iv - v;   // exclusive warp prefix
    }
    __syncthreads();
    int excl = incl - sum + wsum[w];

    int run = excl;
#pragma unroll
    for (int k = 0; k < ITEMS; k++) { g_off[base + k] = run; run += local[k]; }
}

__global__ void scatter_kernel(const float* __restrict__ xyz,
                               const float* __restrict__ aabb, int N) {
    int i = blockIdx.x * blockDim.x + threadIdx.x;
    if (i >= N) return;
    float p[3];
    normalize_p(xyz, aabb, i, p);
    int slot = atomicAdd(&g_off[bin_of(p)], 1);
    g_sorted[slot] = make_float4(p[0], p[1], p[2], __int_as_float(i));
}

// ---------------------------------------------------------------------------
// fp16 vector helpers
// ---------------------------------------------------------------------------
__device__ __forceinline__ void acc8(float* acc, float w, uint4 v) {
    const __half2* h = reinterpret_cast<const __half2*>(&v);
#pragma unroll
    for (int j = 0; j < 4; j++) {
        float2 f = __half22float2(h[j]);
        acc[2 * j + 0] = fmaf(w, f.x, acc[2 * j + 0]);
        acc[2 * j + 1] = fmaf(w, f.y, acc[2 * j + 1]);
    }
}

// ---------------------------------------------------------------------------
// Phase A: per sorted point, compute sigma_feat + rgb, scatter to g_feat.
// ---------------------------------------------------------------------------
__global__ __launch_bounds__(256)
void feature_kernel(const float* __restrict__ wd,     // (1,24)
                    const float* __restrict__ wa,     // (3,72)
                    int N, int G) {
    __shared__ float s_wd[24];
    __shared__ float s_wa[216];

    int gid = blockIdx.x * blockDim.x + threadIdx.x;
    int s = threadIdx.x;
    if (s < 24) s_wd[s] = wd[s];
    for (int j = s; j < 216; j += blockDim.x) s_wa[j] = wa[j];
    __syncthreads();
    if (gid >= N) return;

    float4 sp = g_sorted[gid];
    float p[3] = {sp.x, sp.y, sp.z};
    int oidx = __float_as_int(sp.w);

    int i0[3], i1[3];
    float fr[3];
#pragma unroll
    for (int k = 0; k < 3; k++) {
        float u  = (p[k] + 1.0f) * 0.5f * (float)(G - 1);
        float uf = floorf(u);
        fr[k] = u - uf;
        int a0 = (int)uf;
        a0 = max(0, min(a0, G - 1));
        i0[k] = a0;
        i1[k] = min(a0 + 1, G - 1);
    }

    const int mat_a[3] = {0, 0, 1};
    const int mat_b[3] = {1, 2, 2};
    const int vec_m[3] = {2, 1, 0};

    // ---------------- density ----------------
    float sigma_feat = 0.0f;
#pragma unroll
    for (int i = 0; i < 3; i++) {
        int xa = mat_a[i], yb = mat_b[i], vv = vec_m[i];
        int x0 = i0[xa], x1 = i1[xa], y0 = i0[yb], y1 = i1[yb];
        float wx = fr[xa], wy = fr[yb];
        float w00 = (1.f - wx) * (1.f - wy);
        float w01 = wx * (1.f - wy);
        float w10 = (1.f - wx) * wy;
        float w11 = wx * wy;

        const uint4* gp = reinterpret_cast<const uint4*>(g_dplanesH + (size_t)i * GG * 8);
        float pf[8];
#pragma unroll
        for (int c = 0; c < 8; c++) pf[c] = 0.f;
        acc8(pf, w00, gp[y0 * G + x0]);
        acc8(pf, w01, gp[y0 * G + x1]);
        acc8(pf, w10, gp[y1 * G + x0]);
        acc8(pf, w11, gp[y1 * G + x1]);

        const uint4* gl = reinterpret_cast<const uint4*>(g_dlinesH + (size_t)i * MAXG * 8);
        int t0 = i0[vv], t1 = i1[vv];
        float wt = fr[vv];
        float lf[8];
#pragma unroll
        for (int c = 0; c < 8; c++) lf[c] = 0.f;
        acc8(lf, 1.f - wt, gl[t0]);
        acc8(lf, wt,       gl[t1]);

        const float* w8 = &s_wd[i * 8];
#pragma unroll
        for (int c = 0; c < 8; c++)
            sigma_feat += w8[c] * (pf[c] * lf[c]);
    }

    // ---------------- appearance (rgb), 8-channel chunks ----------------
    float rgb0 = 0.f, rgb1 = 0.f, rgb2 = 0.f;
#pragma unroll
    for (int i = 0; i < 3; i++) {
        int xa = mat_a[i], yb = mat_b[i], vv = vec_m[i];
        int x0 = i0[xa], x1 = i1[xa], y0 = i0[yb], y1 = i1[yb];
        float wx = fr[xa], wy = fr[yb];
        float w00 = (1.f - wx) * (1.f - wy);
        float w01 = wx * (1.f - wy);
        float w10 = (1.f - wx) * wy;
        float w11 = wx * wy;

        const uint4* gp = reinterpret_cast<const uint4*>(g_aplanesH + (size_t)i * GG * 24);
        int o00 = (y0 * G + x0) * 3, o01 = (y0 * G + x1) * 3;
        int o10 = (y1 * G + x0) * 3, o11 = (y1 * G + x1) * 3;

        const uint4* gl = reinterpret_cast<const uint4*>(g_alinesH + (size_t)i * MAXG * 24);
        int t0 = i0[vv] * 3, t1 = i1[vv] * 3;
        float wt = fr[vv];

#pragma unroll
        for (int q = 0; q < 3; q++) {
            float f8[8], l8[8];
#pragma unroll
            for (int c = 0; c < 8; c++) { f8[c] = 0.f; l8[c] = 0.f; }
            acc8(f8, w00, gp[o00 + q]);
            acc8(f8, w01, gp[o01 + q]);
            acc8(f8, w10, gp[o10 + q]);
            acc8(f8, w11, gp[o11 + q]);
            acc8(l8, 1.f - wt, gl[t0 + q]);
            acc8(l8, wt,       gl[t1 + q]);

            const float* wrow = &s_wa[i * 24 + q * 8];
#pragma unroll
            for (int c = 0; c < 8; c++) {
                float fl = f8[c] * l8[c];
                rgb0 = fmaf(wrow[c],       fl, rgb0);
                rgb1 = fmaf(wrow[72 + c],  fl, rgb1);
                rgb2 = fmaf(wrow[144 + c], fl, rgb2);
            }
        }
    }

    g_feat[oidx] = make_float4(sigma_feat, rgb0, rgb1, rgb2);
}

// ---------------------------------------------------------------------------
// Phase B: per-ray alpha compositing. One block per ray.
// ---------------------------------------------------------------------------
__global__ __launch_bounds__(256)
void composite_kernel(const float* __restrict__ z_vals,
                      float* __restrict__ out,          // (Nr,3)
                      int Ns) {
    __shared__ float s_scan[8];
    __shared__ float s_red[8 * 3];

    const int r = blockIdx.x;
    const int s = threadIdx.x;
    const int lane = s & 31;
    const int warp = s >> 5;
    const int idx = r * Ns + s;

    float4 ft = g_feat[idx];

    // dists (fp32, exact subtraction semantics)
    float z_s = z_vals[idx];
    float dist;
    if (s < Ns - 1) dist = z_vals[idx + 1] - z_s;
    else            dist = z_s - z_vals[idx - 1];
    float dist25 = dist * 25.0f;

    // sigma + alpha in DOUBLE precision (fast-math-immune accurate exp).
    double xs  = (double)ft.x - 10.0;
    double sig = fmax(xs, 0.0) + log1p(exp(-fabs(xs)));
    double e   = exp(-sig * (double)dist25);
    float alpha = 1.0f - (float)e;

    // block-wide exclusive product scan for transmittance
    float m = 1.0f - alpha + 1e-10f;
    float v = m;
#pragma unroll
    for (int o = 1; o < 32; o <<= 1) {
        float t = __shfl_up_sync(0xFFFFFFFFu, v, o);
        if (lane >= o) v *= t;
    }
    float excl = __shfl_up_sync(0xFFFFFFFFu, v, 1);
    if (lane == 0) excl = 1.0f;
    if (lane == 31) s_scan[warp] = v;
    __syncthreads();
    float pre = 1.0f;
    for (int w = 0; w < warp; w++) pre *= s_scan[w];
    float T = pre * excl;
    float wgt = alpha * T;

    // weighted rgb reduce
    float a0 = wgt * ft.y, a1 = wgt * ft.z, a2 = wgt * ft.w;
#pragma unroll
    for (int o = 16; o > 0; o >>= 1) {
        a0 += __shfl_xor_sync(0xFFFFFFFFu, a0, o);
        a1 += __shfl_xor_sync(0xFFFFFFFFu, a1, o);
        a2 += __shfl_xor_sync(0xFFFFFFFFu, a2, o);
    }
    if (lane == 0) {
        s_red[warp * 3 + 0] = a0;
        s_red[warp * 3 + 1] = a1;
        s_red[warp * 3 + 2] = a2;
    }
    __syncthreads();
    if (s == 0) {
        float o0 = 0.f, o1 = 0.f, o2 = 0.f;
        int nw = blockDim.x >> 5;
        for (int w = 0; w < nw; w++) {
            o0 += s_red[w * 3 + 0];
            o1 += s_red[w * 3 + 1];
            o2 += s_red[w * 3 + 2];
        }
        out[r * 3 + 0] = o0;
        out[r * 3 + 1] = o1;
        out[r * 3 + 2] = o2;
    }
}

// ---------------------------------------------------------------------------
// Launch
// ---------------------------------------------------------------------------
extern "C" void kernel_launch(void* const* d_in, const int* in_sizes, int n_in,
                              void* d_out, int out_size) {
    const float* xyz_sampled    = (const float*)d_in[0];
    // d_in[1] = viewdirs (unused)
    const float* z_vals         = (const float*)d_in[2];
    const float* density_planes = (const float*)d_in[3];
    const float* density_lines  = (const float*)d_in[4];
    const float* app_planes     = (const float*)d_in[5];
    const float* app_lines      = (const float*)d_in[6];
    const float* density_bw     = (const float*)d_in[7];
    const float* app_bw         = (const float*)d_in[8];
    const float* aabb           = (const float*)d_in[9];
    float* out = (float*)d_out;

    int Nr = in_sizes[1] / 3;
    int Ns = in_sizes[2] / Nr;
    int N  = Nr * Ns;
    int g2 = in_sizes[3] / (3 * 8);
    int G  = (int)(sqrtf((float)g2) + 0.5f);

    int P = G * G;
    // Launch order chosen so ncu -s 5 -c 1 captures feature_kernel.
    {
        dim3 grid((P + 31) / 32, 12);
        transpose_all_kernel<<<grid, 256>>>(density_planes, app_planes,
                                            density_lines, app_lines, G);   // 1
    }
    clear_kernel<<<NBINS / 256, 256>>>();                                   // 2
    hist_kernel<<<(N + 255) / 256, 256>>>(xyz_sampled, aabb, N);            // 3
    scan_kernel<<<1, 1024>>>();                                             // 4
    scatter_kernel<<<(N + 255) / 256, 256>>>(xyz_sampled, aabb, N);         // 5
    feature_kernel<<<(N + 255) / 256, 256>>>(density_bw, app_bw, N, G);     // 6
    composite_kernel<<<Nr, Ns>>>(z_vals, out, Ns);                          // 7
}

// round 11
// speedup vs baseline: 1.4568x; 1.4568x over previous
#include <cuda_runtime.h>
#include <cuda_bf16.h>
#include <cuda_fp16.h>
#include <math.h>
#include <stdint.h>

// ---------------------------------------------------------------------------
// TensoRF_Slim: fused TensoRF feature sampling + volume rendering.
// Round 9: keep R7's Morton-sort + two-phase structure (sort DID cut gather
// wavefronts), but (a) replace the exposed fp64 transcendental chain in
// composite with a cheap exact-rounding-compatible polynomial path
// (~4 fp64 ops/pt instead of ~200 -> composite 170us -> ~10us), and
// (b) replace the 36.5us single-block scan with a 2-level multi-block scan.
// ---------------------------------------------------------------------------

#define MAXG 300
#define GG (MAXG * MAXG)
#define NBINS 32768              // 32^3
#define NSCANBLK 128             // NBINS / 256
#define MAXPTS (4096 * 256)

// Device-global scratch (static allocation; no runtime allocs allowed).
__device__ __align__(16) __half g_dplanesH[3 * GG * 8];    // (3, G*G, 8)
__device__ __align__(16) __half g_aplanesH[3 * GG * 24];   // (3, G*G, 24)
__device__ __align__(16) __half g_dlinesH[3 * MAXG * 8];   // (3, G, 8)
__device__ __align__(16) __half g_alinesH[3 * MAXG * 24];  // (3, G, 24)

__device__ int    g_cnt[NBINS];
__device__ int    g_off[NBINS];     // local (per-chunk) exclusive offsets
__device__ int    g_bsum[NSCANBLK];
__device__ int    g_bpref[NSCANBLK];
__device__ float4 g_sorted[MAXPTS];   // normalized p.xyz + orig idx
__device__ float4 g_feat[MAXPTS];     // sigma_feat, rgb0, rgb1, rgb2

// ---------------------------------------------------------------------------
// Fused transpose: all four tensors (3, C, P) fp32 -> (3, P, C) fp16.
// ---------------------------------------------------------------------------
__global__ void transpose_all_kernel(const float* __restrict__ dp,
                                     const float* __restrict__ ap,
                                     const float* __restrict__ dl,
                                     const float* __restrict__ al,
                                     int G) {
    __shared__ float tile[32][25];
    int type = blockIdx.y / 3;
    int i    = blockIdx.y % 3;

    int P, C;
    const float* src;
    __half* dst;
    switch (type) {
        case 0:  P = G * G; C = 8;  src = dp; dst = g_dplanesH; break;
        case 1:  P = G * G; C = 24; src = ap; dst = g_aplanesH; break;
        case 2:  P = G;     C = 8;  src = dl; dst = g_dlinesH;  break;
        default: P = G;     C = 24; src = al; dst = g_alinesH;  break;
    }
    int p0 = blockIdx.x * 32;
    if (p0 >= P) return;

    src += (size_t)i * C * P;
    dst += (size_t)i * P * C;

    for (int j = threadIdx.x; j < C * 32; j += blockDim.x) {
        int c = j >> 5, pp = j & 31;
        int p = p0 + pp;
        tile[pp][c] = (p < P) ? src[(size_t)c * P + p] : 0.f;
    }
    __syncthreads();
    for (int j = threadIdx.x; j < C * 32; j += blockDim.x) {
        int pp = j / C, c = j - pp * C;
        int p = p0 + pp;
        if (p < P) dst[(size_t)p * C + c] = __float2half_rn(tile[pp][c]);
    }
}

// ---------------------------------------------------------------------------
// Binning: 5-bit Morton per axis -> 15-bit bin.
// ---------------------------------------------------------------------------
__device__ __forceinline__ uint32_t part1by2_5(uint32_t x) {
    x &= 31u;
    x = (x | (x << 8)) & 0x100Fu;
    x = (x | (x << 4)) & 0x10C3u;
    x = (x | (x << 2)) & 0x1249u;
    return x;
}

__device__ __forceinline__ void normalize_p(const float* __restrict__ xyz,
                                            const float* __restrict__ aabb,
                                            int i, float* p) {
#pragma unroll
    for (int k = 0; k < 3; k++) {
        float lo = aabb[k], hi = aabb[3 + k];
        float inv = 2.0f / (hi - lo);
        p[k] = (xyz[i * 3 + k] - lo) * inv - 1.0f;
    }
}

__device__ __forceinline__ uint32_t bin_of(const float* p) {
    uint32_t q[3];
#pragma unroll
    for (int k = 0; k < 3; k++) {
        int v = (int)((p[k] + 1.0f) * 16.0f);
        q[k] = (uint32_t)max(0, min(v, 31));
    }
    return part1by2_5(q[0]) | (part1by2_5(q[1]) << 1) | (part1by2_5(q[2]) << 2);
}

__global__ void hist_kernel(const float* __restrict__ xyz,
                            const float* __restrict__ aabb, int N) {
    int i = blockIdx.x * blockDim.x + threadIdx.x;
    if (i >= N) return;
    float p[3];
    normalize_p(xyz, aabb, i, p);
    atomicAdd(&g_cnt[bin_of(p)], 1);
}

// ---------------------------------------------------------------------------
// Two-level scan. Level A: 128 blocks x 256 thr, each block exclusive-scans
// its 256-bin chunk into g_off, writes chunk total to g_bsum.
// Level B: one block exclusive-scans g_bsum into g_bpref.
// ---------------------------------------------------------------------------
__device__ __forceinline__ int block_excl_scan_256(int v, int t) {
    __shared__ int wsum[8];
    int lane = t & 31, w = t >> 5;
    int incl = v;
#pragma unroll
    for (int o = 1; o < 32; o <<= 1) {
        int u = __shfl_up_sync(0xFFFFFFFFu, incl, o);
        if (lane >= o) incl += u;
    }
    if (lane == 31) wsum[w] = incl;
    __syncthreads();
    if (w == 0 && lane < 8) {
        int x = wsum[lane];
        int ix = x;
#pragma unroll
        for (int o = 1; o < 8; o <<= 1) {
            int u = __shfl_up_sync(0xFFu, ix, o);
            if (lane >= o) ix += u;
        }
        wsum[lane] = ix - x;
    }
    __syncthreads();
    return incl - v + wsum[w];
}

__global__ void scanA_kernel() {
    int b = blockIdx.x, t = threadIdx.x;
    int idx = b * 256 + t;
    int v = g_cnt[idx];
    int excl = block_excl_scan_256(v, t);
    g_off[idx] = excl;
    if (t == 255) g_bsum[b] = excl + v;
}

__global__ void scanB_kernel() {
    int t = threadIdx.x;   // 128 threads
    int lane = t & 31, w = t >> 5;
    __shared__ int wsum[4];
    int v = g_bsum[t];
    int incl = v;
#pragma unroll
    for (int o = 1; o < 32; o <<= 1) {
        int u = __shfl_up_sync(0xFFFFFFFFu, incl, o);
        if (lane >= o) incl += u;
    }
    if (lane == 31) wsum[w] = incl;
    __syncthreads();
    if (t == 0) {
        int run = 0;
        for (int k = 0; k < 4; k++) { int x = wsum[k]; wsum[k] = run; run += x; }
    }
    __syncthreads();
    g_bpref[t] = incl - v + wsum[w];
}

__global__ void scatter_kernel(const float* __restrict__ xyz,
                               const float* __restrict__ aabb, int N) {
    int i = blockIdx.x * blockDim.x + threadIdx.x;
    if (i >= N) return;
    float p[3];
    normalize_p(xyz, aabb, i, p);
    uint32_t b = bin_of(p);
    int slot = g_bpref[b >> 8] + atomicAdd(&g_off[b], 1);
    g_sorted[slot] = make_float4(p[0], p[1], p[2], __int_as_float(i));
}

// ---------------------------------------------------------------------------
// fp16 vector helpers
// ---------------------------------------------------------------------------
__device__ __forceinline__ void acc8(float* acc, float w, uint4 v) {
    const __half2* h = reinterpret_cast<const __half2*>(&v);
#pragma unroll
    for (int j = 0; j < 4; j++) {
        float2 f = __half22float2(h[j]);
        acc[2 * j + 0] = fmaf(w, f.x, acc[2 * j + 0]);
        acc[2 * j + 1] = fmaf(w, f.y, acc[2 * j + 1]);
    }
}

// ---------------------------------------------------------------------------
// Phase A: per sorted point, compute sigma_feat + rgb, scatter to g_feat.
// ---------------------------------------------------------------------------
__global__ __launch_bounds__(256)
void feature_kernel(const float* __restrict__ wd,     // (1,24)
                    const float* __restrict__ wa,     // (3,72)
                    int N, int G) {
    __shared__ float s_wd[24];
    __shared__ float s_wa[216];

    int gid = blockIdx.x * blockDim.x + threadIdx.x;
    int s = threadIdx.x;
    if (s < 24) s_wd[s] = wd[s];
    for (int j = s; j < 216; j += blockDim.x) s_wa[j] = wa[j];
    __syncthreads();
    if (gid >= N) return;

    float4 sp = g_sorted[gid];
    float p[3] = {sp.x, sp.y, sp.z};
    int oidx = __float_as_int(sp.w);

    int i0[3], i1[3];
    float fr[3];
#pragma unroll
    for (int k = 0; k < 3; k++) {
        float u  = (p[k] + 1.0f) * 0.5f * (float)(G - 1);
        float uf = floorf(u);
        fr[k] = u - uf;
        int a0 = (int)uf;
        a0 = max(0, min(a0, G - 1));
        i0[k] = a0;
        i1[k] = min(a0 + 1, G - 1);
    }

    const int mat_a[3] = {0, 0, 1};
    const int mat_b[3] = {1, 2, 2};
    const int vec_m[3] = {2, 1, 0};

    // ---------------- density ----------------
    float sigma_feat = 0.0f;
#pragma unroll
    for (int i = 0; i < 3; i++) {
        int xa = mat_a[i], yb = mat_b[i], vv = vec_m[i];
        int x0 = i0[xa], x1 = i1[xa], y0 = i0[yb], y1 = i1[yb];
        float wx = fr[xa], wy = fr[yb];
        float w00 = (1.f - wx) * (1.f - wy);
        float w01 = wx * (1.f - wy);
        float w10 = (1.f - wx) * wy;
        float w11 = wx * wy;

        const uint4* gp = reinterpret_cast<const uint4*>(g_dplanesH + (size_t)i * GG * 8);
        float pf[8];
#pragma unroll
        for (int c = 0; c < 8; c++) pf[c] = 0.f;
        acc8(pf, w00, gp[y0 * G + x0]);
        acc8(pf, w01, gp[y0 * G + x1]);
        acc8(pf, w10, gp[y1 * G + x0]);
        acc8(pf, w11, gp[y1 * G + x1]);

        const uint4* gl = reinterpret_cast<const uint4*>(g_dlinesH + (size_t)i * MAXG * 8);
        int t0 = i0[vv], t1 = i1[vv];
        float wt = fr[vv];
        float lf[8];
#pragma unroll
        for (int c = 0; c < 8; c++) lf[c] = 0.f;
        acc8(lf, 1.f - wt, gl[t0]);
        acc8(lf, wt,       gl[t1]);

        const float* w8 = &s_wd[i * 8];
#pragma unroll
        for (int c = 0; c < 8; c++)
            sigma_feat += w8[c] * (pf[c] * lf[c]);
    }

    // ---------------- appearance (rgb), 8-channel chunks ----------------
    float rgb0 = 0.f, rgb1 = 0.f, rgb2 = 0.f;
#pragma unroll
    for (int i = 0; i < 3; i++) {
        int xa = mat_a[i], yb = mat_b[i], vv = vec_m[i];
        int x0 = i0[xa], x1 = i1[xa], y0 = i0[yb], y1 = i1[yb];
        float wx = fr[xa], wy = fr[yb];
        float w00 = (1.f - wx) * (1.f - wy);
        float w01 = wx * (1.f - wy);
        float w10 = (1.f - wx) * wy;
        float w11 = wx * wy;

        const uint4* gp = reinterpret_cast<const uint4*>(g_aplanesH + (size_t)i * GG * 24);
        int o00 = (y0 * G + x0) * 3, o01 = (y0 * G + x1) * 3;
        int o10 = (y1 * G + x0) * 3, o11 = (y1 * G + x1) * 3;

        const uint4* gl = reinterpret_cast<const uint4*>(g_alinesH + (size_t)i * MAXG * 24);
        int t0 = i0[vv] * 3, t1 = i1[vv] * 3;
        float wt = fr[vv];

#pragma unroll
        for (int q = 0; q < 3; q++) {
            float f8[8], l8[8];
#pragma unroll
            for (int c = 0; c < 8; c++) { f8[c] = 0.f; l8[c] = 0.f; }
            acc8(f8, w00, gp[o00 + q]);
            acc8(f8, w01, gp[o01 + q]);
            acc8(f8, w10, gp[o10 + q]);
            acc8(f8, w11, gp[o11 + q]);
            acc8(l8, 1.f - wt, gl[t0 + q]);
            acc8(l8, wt,       gl[t1 + q]);

            const float* wrow = &s_wa[i * 24 + q * 8];
#pragma unroll
            for (int c = 0; c < 8; c++) {
                float fl = f8[c] * l8[c];
                rgb0 = fmaf(wrow[c],       fl, rgb0);
                rgb1 = fmaf(wrow[72 + c],  fl, rgb1);
                rgb2 = fmaf(wrow[144 + c], fl, rgb2);
            }
        }
    }

    g_feat[oidx] = make_float4(sigma_feat, rgb0, rgb1, rgb2);
}

// ---------------------------------------------------------------------------
// Phase B: per-ray alpha compositing. One block per ray.
// Cheap alpha path: for xs << 0 and x = sig*dist tiny (always true here),
// softplus via fp32 MUFU exp + log1p poly (no cancellation; rel err ~2e-7),
// and 1-exp(-x) via DOUBLE polynomial 1 - x + x^2/2 - x^3/6 whose f32
// rounding reproduces the reference's 1 - fl32(exp(-x)) exactly.
// Fallback branches use full double exp (never taken with this data).
// ---------------------------------------------------------------------------
__global__ __launch_bounds__(256)
void composite_kernel(const float* __restrict__ z_vals,
                      float* __restrict__ out,          // (Nr,3)
                      int Ns) {
    __shared__ float s_scan[8];
    __shared__ float s_red[8 * 3];

    const int r = blockIdx.x;
    const int s = threadIdx.x;
    const int lane = s & 31;
    const int warp = s >> 5;
    const int idx = r * Ns + s;

    float4 ft = g_feat[idx];

    // dists (fp32, exact subtraction semantics)
    float z_s = z_vals[idx];
    float dist;
    if (s < Ns - 1) dist = z_vals[idx + 1] - z_s;
    else            dist = z_s - z_vals[idx - 1];
    float dist25 = dist * 25.0f;

    // sigma = softplus(sigma_feat - 10)
    float xs = ft.x - 10.0f;
    float sig;
    if (xs < -3.0f) {
        // softplus = log1p(e^xs), e^xs < 0.05: no cancellation, fp32 ok.
        float u = __expf(xs);
        sig = u * (1.0f - u * (0.5f - 0.33333333f * u));
    } else {
        double xd = (double)xs;
        sig = (float)(fmax(xd, 0.0) + log1p(exp(-fabs(xd))));
    }

    double x = (double)sig * (double)dist25;
    float alpha;
    if (x < 1e-3) {
        // exp(-x) poly in double, error < 1e-13; f32 rounding matches ref.
        double e = 1.0 - x * (1.0 - x * (0.5 - x * (1.0 / 6.0)));
        alpha = 1.0f - (float)e;
    } else {
        alpha = 1.0f - (float)exp(-x);
    }

    // block-wide exclusive product scan for transmittance
    float m = 1.0f - alpha + 1e-10f;
    float v = m;
#pragma unroll
    for (int o = 1; o < 32; o <<= 1) {
        float t = __shfl_up_sync(0xFFFFFFFFu, v, o);
        if (lane >= o) v *= t;
    }
    float excl = __shfl_up_sync(0xFFFFFFFFu, v, 1);
    if (lane == 0) excl = 1.0f;
    if (lane == 31) s_scan[warp] = v;
    __syncthreads();
    float pre = 1.0f;
    for (int w = 0; w < warp; w++) pre *= s_scan[w];
    float T = pre * excl;
    float wgt = alpha * T;

    // weighted rgb reduce
    float a0 = wgt * ft.y, a1 = wgt * ft.z, a2 = wgt * ft.w;
#pragma unroll
    for (int o = 16; o > 0; o >>= 1) {
        a0 += __shfl_xor_sync(0xFFFFFFFFu, a0, o);
        a1 += __shfl_xor_sync(0xFFFFFFFFu, a1, o);
        a2 += __shfl_xor_sync(0xFFFFFFFFu, a2, o);
    }
    if (lane == 0) {
        s_red[warp * 3 + 0] = a0;
        s_red[warp * 3 + 1] = a1;
        s_red[warp * 3 + 2] = a2;
    }
    __syncthreads();
    if (s == 0) {
        float o0 = 0.f, o1 = 0.f, o2 = 0.f;
        int nw = blockDim.x >> 5;
        for (int w = 0; w < nw; w++) {
            o0 += s_red[w * 3 + 0];
            o1 += s_red[w * 3 + 1];
            o2 += s_red[w * 3 + 2];
        }
        out[r * 3 + 0] = o0;
        out[r * 3 + 1] = o1;
        out[r * 3 + 2] = o2;
    }
}

// ---------------------------------------------------------------------------
// Launch
// ---------------------------------------------------------------------------
extern "C" void kernel_launch(void* const* d_in, const int* in_sizes, int n_in,
                              void* d_out, int out_size) {
    const float* xyz_sampled    = (const float*)d_in[0];
    // d_in[1] = viewdirs (unused)
    const float* z_vals         = (const float*)d_in[2];
    const float* density_planes = (const float*)d_in[3];
    const float* density_lines  = (const float*)d_in[4];
    const float* app_planes     = (const float*)d_in[5];
    const float* app_lines      = (const float*)d_in[6];
    const float* density_bw     = (const float*)d_in[7];
    const float* app_bw         = (const float*)d_in[8];
    const float* aabb           = (const float*)d_in[9];
    float* out = (float*)d_out;

    int Nr = in_sizes[1] / 3;
    int Ns = in_sizes[2] / Nr;
    int N  = Nr * Ns;
    int g2 = in_sizes[3] / (3 * 8);
    int G  = (int)(sqrtf((float)g2) + 0.5f);

    void* cnt_ptr;
    cudaGetSymbolAddress(&cnt_ptr, g_cnt);

    int P = G * G;
    {
        dim3 grid((P + 31) / 32, 12);
        transpose_all_kernel<<<grid, 256>>>(density_planes, app_planes,
                                            density_lines, app_lines, G);
    }
    cudaMemsetAsync(cnt_ptr, 0, NBINS * sizeof(int));
    hist_kernel<<<(N + 255) / 256, 256>>>(xyz_sampled, aabb, N);
    scanA_kernel<<<NSCANBLK, 256>>>();
    scanB_kernel<<<1, 128>>>();
    scatter_kernel<<<(N + 255) / 256, 256>>>(xyz_sampled, aabb, N);
    feature_kernel<<<(N + 255) / 256, 256>>>(density_bw, app_bw, N, G);
    composite_kernel<<<Nr, Ns>>>(z_vals, out, Ns);
}